// round 3
// baseline (speedup 1.0000x reference)
#include <cuda_runtime.h>

#define N      4096
#define NF     4
#define NC     33           // CHEB_ORDER + 1 coefficients
#define BM     128
#define BN     128
#define BK     8
#define KT     (N / BK)     // 512 k-tiles

// Scratch: 3 ping-pong Chebyshev matrices (T_{k-2}, T_{k-1}, T_k)
__device__ float g_T[3][(size_t)N * N];
// Chebyshev coefficients, pre-scaled by sqrt(N)=64 (and 0.5 folded into c[0])
__device__ float g_coef[NC][NF];

// ---------------------------------------------------------------------------
// Coefficients: c[o][f] = 2/Nc * sum_j cos(pi*o*(j+.5)/Nc) * exp(-tau_f*(cos(pi*(j+.5)/Nc)+1))
// (a1 = a2 = LMAX/2 = 1). Computed in double, stored float, scaled by sqrt(N).
// ---------------------------------------------------------------------------
__global__ void coeff_kernel() {
    const int o = threadIdx.x;
    if (o >= NC) return;
    const double PI = 3.14159265358979323846;
    const double taus[NF] = {0.5, 1.0, 2.0, 4.0};
    double sums[NF] = {0.0, 0.0, 0.0, 0.0};
    for (int j = 0; j < NC; j++) {
        double node = cos(PI * (j + 0.5) / NC);        // Chebyshev node
        double x    = node + 1.0;                      // a1*node + a2
        double t    = cos(PI * (double)o * (j + 0.5) / NC);
        #pragma unroll
        for (int f = 0; f < NF; f++)
            sums[f] += t * exp(-taus[f] * x);
    }
    double scale = (2.0 / NC) * 64.0;                  // * sqrt(4096)
    if (o == 0) scale *= 0.5;                          // r0 uses 0.5*c[0]
    #pragma unroll
    for (int f = 0; f < NF; f++)
        g_coef[o][f] = (float)(scale * sums[f]);
}

// ---------------------------------------------------------------------------
// Init: T0 = I, T1 = L - I, out[f] = c0[f]*I + c1[f]*T1   (c pre-scaled)
// ---------------------------------------------------------------------------
__global__ void init_kernel(const float* __restrict__ L, float* __restrict__ out) {
    size_t v = ((size_t)blockIdx.x * blockDim.x + threadIdx.x) * 4;
    if (v >= (size_t)N * N) return;
    const int i  = (int)(v / N);
    const int j0 = (int)(v % N);

    float4 l = *(const float4*)(L + v);
    float dv[4];
    #pragma unroll
    for (int t = 0; t < 4; t++) dv[t] = (j0 + t == i) ? 1.0f : 0.0f;

    float4 d  = make_float4(dv[0], dv[1], dv[2], dv[3]);
    float4 t1 = make_float4(l.x - dv[0], l.y - dv[1], l.z - dv[2], l.w - dv[3]);

    *(float4*)(&g_T[0][v]) = d;
    *(float4*)(&g_T[1][v]) = t1;

    #pragma unroll
    for (int f = 0; f < NF; f++) {
        float c0 = g_coef[0][f], c1 = g_coef[1][f];
        float4 o;
        o.x = c0 * d.x + c1 * t1.x;
        o.y = c0 * d.y + c1 * t1.y;
        o.z = c0 * d.z + c1 * t1.z;
        o.w = c0 * d.w + c1 * t1.w;
        *(float4*)(out + (size_t)f * N * N + v) = o;
    }
}

// ---------------------------------------------------------------------------
// One recurrence step, fused:
//   G     = L @ T_cur                       (tiled fp32 GEMM)
//   T_new = 2*G - 2*T_cur - T_old           (factor = 2(L - I))
//   out[f] += c[k][f] * T_new               (filter-bank accumulation)
// ---------------------------------------------------------------------------
__global__ __launch_bounds__(256, 2)
void cheb_step_kernel(const float* __restrict__ A,   // L
                      float* __restrict__ out,
                      int k, int icur, int iold, int inew)
{
    const float* __restrict__ B    = g_T[icur];
    const float* __restrict__ Told = g_T[iold];
    float* __restrict__       Tnew = g_T[inew];

    __shared__ float As[2][BK][BM];
    __shared__ float Bs[2][BK][BN];

    const int tid = threadIdx.x;
    const int tx  = tid & 15;        // 0..15  (N direction)
    const int ty  = tid >> 4;        // 0..15  (M direction)
    const int bn0 = blockIdx.x * BN;
    const int bm0 = blockIdx.y * BM;

    // A-tile load map (BM x BK): row = tid/2, 4 k-values
    const int arow = tid >> 1;
    const int acol = (tid & 1) * 4;
    // B-tile load map (BK x BN): row = tid/32, 4 n-values
    const int brow = tid >> 5;
    const int bcol = (tid & 31) * 4;

    const float* Aptr = A + (size_t)(bm0 + arow) * N + acol;
    const float* Bptr = B + (size_t)brow * N + bn0 + bcol;

    float4 aReg = *(const float4*)(Aptr);
    float4 bReg = *(const float4*)(Bptr);

    As[0][acol + 0][arow] = aReg.x;
    As[0][acol + 1][arow] = aReg.y;
    As[0][acol + 2][arow] = aReg.z;
    As[0][acol + 3][arow] = aReg.w;
    *(float4*)&Bs[0][brow][bcol] = bReg;
    __syncthreads();

    float acc[8][8];
    #pragma unroll
    for (int i = 0; i < 8; i++)
        #pragma unroll
        for (int j = 0; j < 8; j++) acc[i][j] = 0.0f;

    #pragma unroll 2
    for (int kt = 0; kt < KT; kt++) {
        const int buf = kt & 1;
        if (kt + 1 < KT) {   // prefetch next tile into registers
            aReg = *(const float4*)(Aptr + (kt + 1) * BK);
            bReg = *(const float4*)(Bptr + (size_t)(kt + 1) * BK * N);
        }
        #pragma unroll
        for (int kk = 0; kk < BK; kk++) {
            float a[8], b[8];
            *(float4*)&a[0] = *(const float4*)&As[buf][kk][ty * 8];
            *(float4*)&a[4] = *(const float4*)&As[buf][kk][ty * 8 + 4];
            *(float4*)&b[0] = *(const float4*)&Bs[buf][kk][tx * 8];
            *(float4*)&b[4] = *(const float4*)&Bs[buf][kk][tx * 8 + 4];
            #pragma unroll
            for (int i = 0; i < 8; i++)
                #pragma unroll
                for (int j = 0; j < 8; j++)
                    acc[i][j] += a[i] * b[j];
        }
        if (kt + 1 < KT) {
            const int nb = buf ^ 1;
            As[nb][acol + 0][arow] = aReg.x;
            As[nb][acol + 1][arow] = aReg.y;
            As[nb][acol + 2][arow] = aReg.z;
            As[nb][acol + 3][arow] = aReg.w;
            *(float4*)&Bs[nb][brow][bcol] = bReg;
            __syncthreads();
        }
    }

    // Fused epilogue
    const float cf0 = g_coef[k][0];
    const float cf1 = g_coef[k][1];
    const float cf2 = g_coef[k][2];
    const float cf3 = g_coef[k][3];
    const size_t NN = (size_t)N * N;

    #pragma unroll
    for (int i = 0; i < 8; i++) {
        const int row = bm0 + ty * 8 + i;
        const size_t base = (size_t)row * N + bn0 + tx * 8;
        #pragma unroll
        for (int jq = 0; jq < 2; jq++) {
            const size_t idx = base + jq * 4;
            float4 cur = *(const float4*)(B + idx);
            float4 old = *(const float4*)(Told + idx);
            float4 tn;
            tn.x = 2.0f * acc[i][jq * 4 + 0] - 2.0f * cur.x - old.x;
            tn.y = 2.0f * acc[i][jq * 4 + 1] - 2.0f * cur.y - old.y;
            tn.z = 2.0f * acc[i][jq * 4 + 2] - 2.0f * cur.z - old.z;
            tn.w = 2.0f * acc[i][jq * 4 + 3] - 2.0f * cur.w - old.w;
            *(float4*)(Tnew + idx) = tn;

            {
                float4 o = *(const float4*)(out + idx);
                o.x += cf0 * tn.x; o.y += cf0 * tn.y; o.z += cf0 * tn.z; o.w += cf0 * tn.w;
                *(float4*)(out + idx) = o;
            }
            {
                float4 o = *(const float4*)(out + NN + idx);
                o.x += cf1 * tn.x; o.y += cf1 * tn.y; o.z += cf1 * tn.z; o.w += cf1 * tn.w;
                *(float4*)(out + NN + idx) = o;
            }
            {
                float4 o = *(const float4*)(out + 2 * NN + idx);
                o.x += cf2 * tn.x; o.y += cf2 * tn.y; o.z += cf2 * tn.z; o.w += cf2 * tn.w;
                *(float4*)(out + 2 * NN + idx) = o;
            }
            {
                float4 o = *(const float4*)(out + 3 * NN + idx);
                o.x += cf3 * tn.x; o.y += cf3 * tn.y; o.z += cf3 * tn.z; o.w += cf3 * tn.w;
                *(float4*)(out + 3 * NN + idx) = o;
            }
        }
    }
}

// ---------------------------------------------------------------------------
extern "C" void kernel_launch(void* const* d_in, const int* in_sizes, int n_in,
                              void* d_out, int out_size)
{
    const float* L = (const float*)d_in[0];
    float* out = (float*)d_out;

    coeff_kernel<<<1, 64>>>();

    {
        const size_t nvec = ((size_t)N * N) / 4;
        const int threads = 256;
        const int blocks = (int)((nvec + threads - 1) / threads);
        init_kernel<<<blocks, threads>>>(L, out);
    }

    dim3 grid(N / BN, N / BM);
    for (int k = 2; k <= 32; k++) {
        cheb_step_kernel<<<grid, 256>>>(L, out, k, (k - 1) % 3, (k - 2) % 3, k % 3);
    }
}

// round 11
// speedup vs baseline: 2.2618x; 2.2618x over previous
#include <cuda_runtime.h>
#include <cuda_bf16.h>
#include <stdint.h>

#define N      4096
#define NF     4
#define NC     33
#define KC     64                  // K elements per pipeline stage
#define NCHUNK (N / KC)            // 64
#define NSTAGE 3
#define TILE_B (128 * 128)         // 128 rows x 128 bytes = 16 KB per matrix tile
#define STAGE_B (4 * TILE_B)       // Ah, Al, Bh, Bl = 64 KB
#define SMEM_BYTES (NSTAGE * STAGE_B)   // 192 KB

// ---------------- device globals (scratch; no allocation allowed) ----------
__device__ __align__(1024) float          g_Tf[2][(size_t)N * N];  // fp32 T ping-pong
__device__ __align__(1024) __nv_bfloat16  g_Bh[2][(size_t)N * N];  // T split hi
__device__ __align__(1024) __nv_bfloat16  g_Bl[2][(size_t)N * N];  // T split lo
__device__ __align__(1024) __nv_bfloat16  g_Fh[(size_t)N * N];     // F = 2(L-I) hi
__device__ __align__(1024) __nv_bfloat16  g_Fl[(size_t)N * N];     // F lo
__device__ float g_coef[NC][NF];

// ---------------- PTX helpers (baseline sm_80+ PTX only) -------------------
__device__ __forceinline__ uint32_t smem_u32(const void* p) {
    uint32_t a;
    asm("{ .reg .u64 t; cvta.to.shared.u64 t, %1; cvt.u32.u64 %0, t; }" : "=r"(a) : "l"(p));
    return a;
}

#define CP_ASYNC16(dst, src) \
    asm volatile("cp.async.cg.shared.global [%0], [%1], 16;" :: "r"(dst), "l"(src) : "memory")
#define CP_COMMIT() asm volatile("cp.async.commit_group;" ::: "memory")
#define CP_WAIT(n)  asm volatile("cp.async.wait_group %0;" :: "n"(n) : "memory")

#define LDSM_X4(r, addr)                                                     \
    asm volatile("ldmatrix.sync.aligned.m8n8.x4.shared.b16 {%0,%1,%2,%3}, [%4];" \
        : "=r"((r)[0]), "=r"((r)[1]), "=r"((r)[2]), "=r"((r)[3]) : "r"(addr))
#define LDSM_X2(r, addr)                                                     \
    asm volatile("ldmatrix.sync.aligned.m8n8.x2.shared.b16 {%0,%1}, [%2];"   \
        : "=r"((r)[0]), "=r"((r)[1]) : "r"(addr))

#define MMA_BF16(c, a, b)                                                    \
    asm volatile("mma.sync.aligned.m16n8k16.row.col.f32.bf16.bf16.f32 "      \
        "{%0,%1,%2,%3}, {%4,%5,%6,%7}, {%8,%9}, {%0,%1,%2,%3};"              \
        : "+f"((c)[0]), "+f"((c)[1]), "+f"((c)[2]), "+f"((c)[3])             \
        : "r"((a)[0]), "r"((a)[1]), "r"((a)[2]), "r"((a)[3]),                \
          "r"((b)[0]), "r"((b)[1]))

// ---------------- coefficients --------------------------------------------
__global__ void coeff_kernel() {
    const int o = threadIdx.x;
    if (o >= NC) return;
    const double PI = 3.14159265358979323846;
    const double taus[NF] = {0.5, 1.0, 2.0, 4.0};
    double sums[NF] = {0, 0, 0, 0};
    for (int j = 0; j < NC; j++) {
        double node = cos(PI * (j + 0.5) / NC);
        double x    = node + 1.0;
        double t    = cos(PI * (double)o * (j + 0.5) / NC);
        #pragma unroll
        for (int f = 0; f < NF; f++) sums[f] += t * exp(-taus[f] * x);
    }
    double scale = (2.0 / NC) * 64.0;     // * sqrt(4096)
    if (o == 0) scale *= 0.5;
    #pragma unroll
    for (int f = 0; f < NF; f++) g_coef[o][f] = (float)(scale * sums[f]);
}

// ---------------- init: T0=I, T1=L-I, F=2(L-I), splits, out init -----------
__global__ void init_kernel(const float* __restrict__ L, float* __restrict__ out) {
    size_t v = ((size_t)blockIdx.x * blockDim.x + threadIdx.x) * 4;
    if (v >= (size_t)N * N) return;
    const int i  = (int)(v / N);
    const int j0 = (int)(v % N);
    float4 l = *(const float4*)(L + v);
    float d[4], t1[4];
    #pragma unroll
    for (int t = 0; t < 4; t++) d[t] = (j0 + t == i) ? 1.0f : 0.0f;
    t1[0] = l.x - d[0]; t1[1] = l.y - d[1]; t1[2] = l.z - d[2]; t1[3] = l.w - d[3];

    *(float4*)(&g_Tf[0][v]) = make_float4(d[0], d[1], d[2], d[3]);
    *(float4*)(&g_Tf[1][v]) = make_float4(t1[0], t1[1], t1[2], t1[3]);

    #pragma unroll
    for (int t = 0; t < 4; t++) {
        __nv_bfloat16 h  = __float2bfloat16(t1[t]);
        __nv_bfloat16 lo = __float2bfloat16(t1[t] - __bfloat162float(h));
        g_Bh[0][v + t] = h; g_Bl[0][v + t] = lo;
        float f = 2.0f * t1[t];
        __nv_bfloat16 fh = __float2bfloat16(f);
        __nv_bfloat16 fl = __float2bfloat16(f - __bfloat162float(fh));
        g_Fh[v + t] = fh; g_Fl[v + t] = fl;
    }
    #pragma unroll
    for (int f = 0; f < NF; f++) {
        float c0 = g_coef[0][f], c1 = g_coef[1][f];
        float4 o;
        o.x = c0 * d[0] + c1 * t1[0];
        o.y = c0 * d[1] + c1 * t1[1];
        o.z = c0 * d[2] + c1 * t1[2];
        o.w = c0 * d[3] + c1 * t1[3];
        *(float4*)(out + (size_t)f * N * N + v) = o;
    }
}

// ---------------- main step: D = F @ Tcur (bf16x3 mma.sync), fused epilogue
// D[m][n] = sum_k F[m][k] * Tcur[n][k]  (Tcur symmetric => equals F @ Tcur)
__global__ __launch_bounds__(256, 1)
void cheb_step_kernel(float* __restrict__ out, int k, int rb, int wb, int tf)
{
    extern __shared__ __align__(128) char smem[];
    const uint32_t sbase = smem_u32(smem);
    const int tid  = threadIdx.x;
    const int wid  = tid >> 5;
    const int lane = tid & 31;
    const int wm   = wid >> 2;        // 0..1  (M direction, 64 rows each)
    const int wn   = wid & 3;         // 0..3  (N direction, 32 cols each)
    const int bn0  = blockIdx.x * 128;
    const int bm0  = blockIdx.y * 128;

    const __nv_bfloat16* srcs[4];
    srcs[0] = g_Fh     + (size_t)bm0 * N;
    srcs[1] = g_Fl     + (size_t)bm0 * N;
    srcs[2] = g_Bh[rb] + (size_t)bn0 * N;
    srcs[3] = g_Bl[rb] + (size_t)bn0 * N;

    // stage fill: 4 tiles x 128 rows x 8 segs of 16B, xor-swizzled per row
    auto load_stage = [&](int s, int chunk) {
        const uint32_t sb   = sbase + s * STAGE_B;
        const size_t   koff = (size_t)chunk * KC;
        #pragma unroll
        for (int t = 0; t < 4; t++) {
            const uint32_t tb = sb + t * TILE_B;
            const __nv_bfloat16* src = srcs[t] + koff;
            #pragma unroll
            for (int q = 0; q < 4; q++) {
                const int s16 = tid + q * 256;          // 0..1023
                const int row = s16 >> 3, seg = s16 & 7;
                CP_ASYNC16(tb + row * 128 + ((seg ^ (row & 7)) << 4),
                           src + (size_t)row * N + seg * 8);
            }
        }
    };

    float acc[4][4][4];
    #pragma unroll
    for (int mt = 0; mt < 4; mt++)
        #pragma unroll
        for (int nt = 0; nt < 4; nt++)
            #pragma unroll
            for (int q = 0; q < 4; q++) acc[mt][nt][q] = 0.0f;

    load_stage(0, 0); CP_COMMIT();
    load_stage(1, 1); CP_COMMIT();

    const int arow_l = lane & 15;           // A ldmatrix row-in-tile
    const int asub   = lane >> 4;           // A 16B sub-segment (k half)
    const int brow_l = lane & 7;            // B ldmatrix row-in-tile
    const int bsub   = (lane >> 3) & 1;

    for (int i = 0; i < NCHUNK; i++) {
        CP_WAIT(1);
        __syncthreads();                    // stage i landed; i-1 compute done
        if (i + 2 < NCHUNK) load_stage((i + 2) % NSTAGE, i + 2);
        CP_COMMIT();

        const uint32_t stb = sbase + (i % NSTAGE) * STAGE_B;
        const uint32_t Ah = stb;
        const uint32_t Al = stb + TILE_B;
        const uint32_t Bh = stb + 2 * TILE_B;
        const uint32_t Bl = stb + 3 * TILE_B;

        #pragma unroll
        for (int ks = 0; ks < 4; ks++) {    // 4 x k16 within the 64-chunk
            uint32_t ah[4][4], al[4][4], b[4][2];
            #pragma unroll
            for (int mt = 0; mt < 4; mt++) {
                const int row = wm * 64 + mt * 16 + arow_l;
                const int seg = ks * 2 + asub;
                const uint32_t off = row * 128 + ((seg ^ (row & 7)) << 4);
                LDSM_X4(ah[mt], Ah + off);
                LDSM_X4(al[mt], Al + off);
            }
            #pragma unroll
            for (int nt = 0; nt < 4; nt++) {
                const int row = wn * 32 + nt * 8 + brow_l;
                const int seg = ks * 2 + bsub;
                LDSM_X2(b[nt], Bh + row * 128 + ((seg ^ (row & 7)) << 4));
            }
            #pragma unroll
            for (int mt = 0; mt < 4; mt++)
                #pragma unroll
                for (int nt = 0; nt < 4; nt++) {
                    MMA_BF16(acc[mt][nt], ah[mt], b[nt]);   // Ah*Bh
                    MMA_BF16(acc[mt][nt], al[mt], b[nt]);   // Al*Bh
                }
            #pragma unroll
            for (int nt = 0; nt < 4; nt++) {
                const int row = wn * 32 + nt * 8 + brow_l;
                const int seg = ks * 2 + bsub;
                LDSM_X2(b[nt], Bl + row * 128 + ((seg ^ (row & 7)) << 4));
            }
            #pragma unroll
            for (int mt = 0; mt < 4; mt++)
                #pragma unroll
                for (int nt = 0; nt < 4; nt++)
                    MMA_BF16(acc[mt][nt], ah[mt], b[nt]);   // Ah*Bl
        }
    }

    // ---------------- fused epilogue (register accumulators) ---------------
    float* __restrict__ Tf = g_Tf[tf];                // Told in, Tnew out (in place)
    __nv_bfloat16* __restrict__ BhO = g_Bh[wb];
    __nv_bfloat16* __restrict__ BlO = g_Bl[wb];
    const float c0 = g_coef[k][0], c1 = g_coef[k][1];
    const float c2 = g_coef[k][2], c3 = g_coef[k][3];
    const size_t NN = (size_t)N * N;

    #pragma unroll
    for (int mt = 0; mt < 4; mt++) {
        const int r0 = bm0 + wm * 64 + mt * 16 + (lane >> 2);
        #pragma unroll
        for (int nt = 0; nt < 4; nt++) {
            const int col = bn0 + wn * 32 + nt * 8 + (lane & 3) * 2;
            #pragma unroll
            for (int p = 0; p < 2; p++) {             // rows r0 and r0+8
                const size_t idx = (size_t)(r0 + p * 8) * N + col;
                float2 told = *(const float2*)(Tf + idx);
                const float tnx = acc[mt][nt][p * 2 + 0] - told.x;
                const float tny = acc[mt][nt][p * 2 + 1] - told.y;
                *(float2*)(Tf + idx) = make_float2(tnx, tny);

                __nv_bfloat16 hx = __float2bfloat16(tnx);
                __nv_bfloat16 hy = __float2bfloat16(tny);
                __nv_bfloat16 lx = __float2bfloat16(tnx - __bfloat162float(hx));
                __nv_bfloat16 ly = __float2bfloat16(tny - __bfloat162float(hy));
                *(__nv_bfloat162*)(BhO + idx) = __nv_bfloat162(hx, hy);
                *(__nv_bfloat162*)(BlO + idx) = __nv_bfloat162(lx, ly);

                float2 o;
                o = *(const float2*)(out + idx);
                o.x += c0 * tnx; o.y += c0 * tny;
                *(float2*)(out + idx) = o;
                o = *(const float2*)(out + NN + idx);
                o.x += c1 * tnx; o.y += c1 * tny;
                *(float2*)(out + NN + idx) = o;
                o = *(const float2*)(out + 2 * NN + idx);
                o.x += c2 * tnx; o.y += c2 * tny;
                *(float2*)(out + 2 * NN + idx) = o;
                o = *(const float2*)(out + 3 * NN + idx);
                o.x += c3 * tnx; o.y += c3 * tny;
                *(float2*)(out + 3 * NN + idx) = o;
            }
        }
    }
}

// ---------------------------------------------------------------------------
extern "C" void kernel_launch(void* const* d_in, const int* in_sizes, int n_in,
                              void* d_out, int out_size)
{
    const float* L = (const float*)d_in[0];
    float* out = (float*)d_out;

    cudaFuncSetAttribute(cheb_step_kernel,
                         cudaFuncAttributeMaxDynamicSharedMemorySize, SMEM_BYTES);

    coeff_kernel<<<1, 64>>>();
    init_kernel<<<(int)(((size_t)N * N / 4 + 255) / 256), 256>>>(L, out);

    dim3 grid(N / 128, N / 128);
    for (int k = 2; k <= 32; k++) {
        // rb: split buffer written by previous step (T_{k-1});
        // wb: buffer this step writes (T_k); tf: fp32 buffer holding T_{k-2}
        cheb_step_kernel<<<grid, 256, SMEM_BYTES>>>(out, k, k & 1, (k + 1) & 1, k & 1);
    }
}

// round 12
// speedup vs baseline: 2.5604x; 1.1320x over previous
#include <cuda_runtime.h>
#include <cuda_bf16.h>
#include <stdint.h>

#define N      4096
#define NF     4
#define NC     33
#define KC     64                  // K elements per pipeline stage
#define NCHUNK (N / KC)            // 64
#define NSTAGE 3
#define TILE_B (128 * 128)         // 128 rows x 128 bytes = 16 KB per matrix tile
#define STAGE_B (4 * TILE_B)       // Ah, Al, Bh, Bl = 64 KB
#define SMEM_BYTES (NSTAGE * STAGE_B)   // 192 KB
#define NTHREADS 512

// ---------------- device globals (scratch; no allocation allowed) ----------
__device__ __align__(1024) float          g_Tf[2][(size_t)N * N];  // fp32 T ping-pong
__device__ __align__(1024) __nv_bfloat16  g_Bh[2][(size_t)N * N];  // T split hi
__device__ __align__(1024) __nv_bfloat16  g_Bl[2][(size_t)N * N];  // T split lo
__device__ __align__(1024) __nv_bfloat16  g_Fh[(size_t)N * N];     // F = 2(L-I) hi
__device__ __align__(1024) __nv_bfloat16  g_Fl[(size_t)N * N];     // F lo
__device__ float g_coef[NC][NF];

// ---------------- PTX helpers (baseline sm_80+ PTX only) -------------------
__device__ __forceinline__ uint32_t smem_u32(const void* p) {
    uint32_t a;
    asm("{ .reg .u64 t; cvta.to.shared.u64 t, %1; cvt.u32.u64 %0, t; }" : "=r"(a) : "l"(p));
    return a;
}

#define CP_ASYNC16(dst, src) \
    asm volatile("cp.async.cg.shared.global [%0], [%1], 16;" :: "r"(dst), "l"(src) : "memory")
#define CP_COMMIT() asm volatile("cp.async.commit_group;" ::: "memory")
#define CP_WAIT(n)  asm volatile("cp.async.wait_group %0;" :: "n"(n) : "memory")

#define LDSM_X4(r, addr)                                                     \
    asm volatile("ldmatrix.sync.aligned.m8n8.x4.shared.b16 {%0,%1,%2,%3}, [%4];" \
        : "=r"((r)[0]), "=r"((r)[1]), "=r"((r)[2]), "=r"((r)[3]) : "r"(addr))
#define LDSM_X2(r, addr)                                                     \
    asm volatile("ldmatrix.sync.aligned.m8n8.x2.shared.b16 {%0,%1}, [%2];"   \
        : "=r"((r)[0]), "=r"((r)[1]) : "r"(addr))

#define MMA_BF16(c, a, b)                                                    \
    asm volatile("mma.sync.aligned.m16n8k16.row.col.f32.bf16.bf16.f32 "      \
        "{%0,%1,%2,%3}, {%4,%5,%6,%7}, {%8,%9}, {%0,%1,%2,%3};"              \
        : "+f"((c)[0]), "+f"((c)[1]), "+f"((c)[2]), "+f"((c)[3])             \
        : "r"((a)[0]), "r"((a)[1]), "r"((a)[2]), "r"((a)[3]),                \
          "r"((b)[0]), "r"((b)[1]))

// ---------------- coefficients --------------------------------------------
__global__ void coeff_kernel() {
    const int o = threadIdx.x;
    if (o >= NC) return;
    const double PI = 3.14159265358979323846;
    const double taus[NF] = {0.5, 1.0, 2.0, 4.0};
    double sums[NF] = {0, 0, 0, 0};
    for (int j = 0; j < NC; j++) {
        double node = cos(PI * (j + 0.5) / NC);
        double x    = node + 1.0;
        double t    = cos(PI * (double)o * (j + 0.5) / NC);
        #pragma unroll
        for (int f = 0; f < NF; f++) sums[f] += t * exp(-taus[f] * x);
    }
    double scale = (2.0 / NC) * 64.0;     // * sqrt(4096)
    if (o == 0) scale *= 0.5;
    #pragma unroll
    for (int f = 0; f < NF; f++) g_coef[o][f] = (float)(scale * sums[f]);
}

// ---------------- init: T0=I, T1=L-I, F=2(L-I), splits, out init -----------
__global__ void init_kernel(const float* __restrict__ L, float* __restrict__ out) {
    size_t v = ((size_t)blockIdx.x * blockDim.x + threadIdx.x) * 4;
    if (v >= (size_t)N * N) return;
    const int i  = (int)(v / N);
    const int j0 = (int)(v % N);
    float4 l = *(const float4*)(L + v);
    float d[4], t1[4];
    #pragma unroll
    for (int t = 0; t < 4; t++) d[t] = (j0 + t == i) ? 1.0f : 0.0f;
    t1[0] = l.x - d[0]; t1[1] = l.y - d[1]; t1[2] = l.z - d[2]; t1[3] = l.w - d[3];

    *(float4*)(&g_Tf[0][v]) = make_float4(d[0], d[1], d[2], d[3]);
    *(float4*)(&g_Tf[1][v]) = make_float4(t1[0], t1[1], t1[2], t1[3]);

    #pragma unroll
    for (int t = 0; t < 4; t++) {
        __nv_bfloat16 h  = __float2bfloat16(t1[t]);
        __nv_bfloat16 lo = __float2bfloat16(t1[t] - __bfloat162float(h));
        g_Bh[0][v + t] = h; g_Bl[0][v + t] = lo;
        float f = 2.0f * t1[t];
        __nv_bfloat16 fh = __float2bfloat16(f);
        __nv_bfloat16 fl = __float2bfloat16(f - __bfloat162float(fh));
        g_Fh[v + t] = fh; g_Fl[v + t] = fl;
    }
    #pragma unroll
    for (int f = 0; f < NF; f++) {
        float c0 = g_coef[0][f], c1 = g_coef[1][f];
        float4 o;
        o.x = c0 * d[0] + c1 * t1[0];
        o.y = c0 * d[1] + c1 * t1[1];
        o.z = c0 * d[2] + c1 * t1[2];
        o.w = c0 * d[3] + c1 * t1[3];
        *(float4*)(out + (size_t)f * N * N + v) = o;
    }
}

// ---------------- main step: D = F @ Tcur (bf16x3 mma.sync), fused epilogue
// D[m][n] = sum_k F[m][k] * Tcur[n][k]  (Tcur symmetric => equals F @ Tcur)
// 16 warps in a 4x4 grid; each warp owns a 32x32 output tile (2 mt x 4 nt).
__global__ __launch_bounds__(NTHREADS, 1)
void cheb_step_kernel(float* __restrict__ out, int k, int rb, int wb, int tf)
{
    extern __shared__ __align__(128) char smem[];
    const uint32_t sbase = smem_u32(smem);
    const int tid  = threadIdx.x;
    const int wid  = tid >> 5;
    const int lane = tid & 31;
    const int wm   = wid >> 2;        // 0..3  (M direction, 32 rows each)
    const int wn   = wid & 3;         // 0..3  (N direction, 32 cols each)
    const int bn0  = blockIdx.x * 128;
    const int bm0  = blockIdx.y * 128;

    const __nv_bfloat16* srcs[4];
    srcs[0] = g_Fh     + (size_t)bm0 * N;
    srcs[1] = g_Fl     + (size_t)bm0 * N;
    srcs[2] = g_Bh[rb] + (size_t)bn0 * N;
    srcs[3] = g_Bl[rb] + (size_t)bn0 * N;

    // stage fill: 4 tiles x 128 rows x 8 segs of 16B, xor-swizzled per row.
    // 4096 segments / 512 threads = 8 per thread (t-loop x q-loop).
    auto load_stage = [&](int s, int chunk) {
        const uint32_t sb   = sbase + s * STAGE_B;
        const size_t   koff = (size_t)chunk * KC;
        #pragma unroll
        for (int t = 0; t < 4; t++) {
            const uint32_t tb = sb + t * TILE_B;
            const __nv_bfloat16* src = srcs[t] + koff;
            #pragma unroll
            for (int q = 0; q < 2; q++) {
                const int s16 = tid + q * NTHREADS;     // 0..1023
                const int row = s16 >> 3, seg = s16 & 7;
                CP_ASYNC16(tb + row * 128 + ((seg ^ (row & 7)) << 4),
                           src + (size_t)row * N + seg * 8);
            }
        }
    };

    float acc[2][4][4];
    #pragma unroll
    for (int mt = 0; mt < 2; mt++)
        #pragma unroll
        for (int nt = 0; nt < 4; nt++)
            #pragma unroll
            for (int q = 0; q < 4; q++) acc[mt][nt][q] = 0.0f;

    load_stage(0, 0); CP_COMMIT();
    load_stage(1, 1); CP_COMMIT();

    const int arow_l = lane & 15;           // A ldmatrix row-in-tile
    const int asub   = lane >> 4;           // A 16B sub-segment (k half)
    const int brow_l = lane & 7;            // B ldmatrix row-in-tile
    const int bsub   = (lane >> 3) & 1;

    for (int i = 0; i < NCHUNK; i++) {
        CP_WAIT(1);
        __syncthreads();                    // stage i landed; i-1 compute done
        if (i + 2 < NCHUNK) load_stage((i + 2) % NSTAGE, i + 2);
        CP_COMMIT();

        const uint32_t stb = sbase + (i % NSTAGE) * STAGE_B;
        const uint32_t Ah = stb;
        const uint32_t Al = stb + TILE_B;
        const uint32_t Bh = stb + 2 * TILE_B;
        const uint32_t Bl = stb + 3 * TILE_B;

        #pragma unroll
        for (int ks = 0; ks < 4; ks++) {    // 4 x k16 within the 64-chunk
            uint32_t ah[2][4], al[2][4], b[4][2];
            // ---- pass 1: Ah * Bh (8 independent MMAs) ----
            #pragma unroll
            for (int mt = 0; mt < 2; mt++) {
                const int row = wm * 32 + mt * 16 + arow_l;
                const int seg = ks * 2 + asub;
                LDSM_X4(ah[mt], Ah + row * 128 + ((seg ^ (row & 7)) << 4));
            }
            #pragma unroll
            for (int nt = 0; nt < 4; nt++) {
                const int row = wn * 32 + nt * 8 + brow_l;
                const int seg = ks * 2 + bsub;
                LDSM_X2(b[nt], Bh + row * 128 + ((seg ^ (row & 7)) << 4));
            }
            #pragma unroll
            for (int mt = 0; mt < 2; mt++)
                #pragma unroll
                for (int nt = 0; nt < 4; nt++)
                    MMA_BF16(acc[mt][nt], ah[mt], b[nt]);   // Ah*Bh

            // ---- pass 2: Al * Bh (reuse b; 8 independent MMAs) ----
            #pragma unroll
            for (int mt = 0; mt < 2; mt++) {
                const int row = wm * 32 + mt * 16 + arow_l;
                const int seg = ks * 2 + asub;
                LDSM_X4(al[mt], Al + row * 128 + ((seg ^ (row & 7)) << 4));
            }
            #pragma unroll
            for (int mt = 0; mt < 2; mt++)
                #pragma unroll
                for (int nt = 0; nt < 4; nt++)
                    MMA_BF16(acc[mt][nt], al[mt], b[nt]);   // Al*Bh

            // ---- pass 3: Ah * Bl (reuse ah; 8 independent MMAs) ----
            #pragma unroll
            for (int nt = 0; nt < 4; nt++) {
                const int row = wn * 32 + nt * 8 + brow_l;
                const int seg = ks * 2 + bsub;
                LDSM_X2(b[nt], Bl + row * 128 + ((seg ^ (row & 7)) << 4));
            }
            #pragma unroll
            for (int mt = 0; mt < 2; mt++)
                #pragma unroll
                for (int nt = 0; nt < 4; nt++)
                    MMA_BF16(acc[mt][nt], ah[mt], b[nt]);   // Ah*Bl
        }
    }

    // ---------------- fused epilogue (register accumulators) ---------------
    float* __restrict__ Tf = g_Tf[tf];                // Told in, Tnew out (in place)
    __nv_bfloat16* __restrict__ BhO = g_Bh[wb];
    __nv_bfloat16* __restrict__ BlO = g_Bl[wb];
    const float c0 = g_coef[k][0], c1 = g_coef[k][1];
    const float c2 = g_coef[k][2], c3 = g_coef[k][3];
    const size_t NN = (size_t)N * N;

    #pragma unroll
    for (int mt = 0; mt < 2; mt++) {
        const int r0 = bm0 + wm * 32 + mt * 16 + (lane >> 2);
        #pragma unroll
        for (int nt = 0; nt < 4; nt++) {
            const int col = bn0 + wn * 32 + nt * 8 + (lane & 3) * 2;
            #pragma unroll
            for (int p = 0; p < 2; p++) {             // rows r0 and r0+8
                const size_t idx = (size_t)(r0 + p * 8) * N + col;
                float2 told = *(const float2*)(Tf + idx);
                const float tnx = acc[mt][nt][p * 2 + 0] - told.x;
                const float tny = acc[mt][nt][p * 2 + 1] - told.y;
                *(float2*)(Tf + idx) = make_float2(tnx, tny);

                __nv_bfloat16 hx = __float2bfloat16(tnx);
                __nv_bfloat16 hy = __float2bfloat16(tny);
                __nv_bfloat16 lx = __float2bfloat16(tnx - __bfloat162float(hx));
                __nv_bfloat16 ly = __float2bfloat16(tny - __bfloat162float(hy));
                *(__nv_bfloat162*)(BhO + idx) = __nv_bfloat162(hx, hy);
                *(__nv_bfloat162*)(BlO + idx) = __nv_bfloat162(lx, ly);

                float2 o;
                o = *(const float2*)(out + idx);
                o.x += c0 * tnx; o.y += c0 * tny;
                *(float2*)(out + idx) = o;
                o = *(const float2*)(out + NN + idx);
                o.x += c1 * tnx; o.y += c1 * tny;
                *(float2*)(out + NN + idx) = o;
                o = *(const float2*)(out + 2 * NN + idx);
                o.x += c2 * tnx; o.y += c2 * tny;
                *(float2*)(out + 2 * NN + idx) = o;
                o = *(const float2*)(out + 3 * NN + idx);
                o.x += c3 * tnx; o.y += c3 * tny;
                *(float2*)(out + 3 * NN + idx) = o;
            }
        }
    }
}

// ---------------------------------------------------------------------------
extern "C" void kernel_launch(void* const* d_in, const int* in_sizes, int n_in,
                              void* d_out, int out_size)
{
    const float* L = (const float*)d_in[0];
    float* out = (float*)d_out;

    cudaFuncSetAttribute(cheb_step_kernel,
                         cudaFuncAttributeMaxDynamicSharedMemorySize, SMEM_BYTES);

    coeff_kernel<<<1, 64>>>();
    init_kernel<<<(int)(((size_t)N * N / 4 + 255) / 256), 256>>>(L, out);

    dim3 grid(N / 128, N / 128);
    for (int k = 2; k <= 32; k++) {
        // rb: split buffer written by previous step (T_{k-1});
        // wb: buffer this step writes (T_k); tf: fp32 buffer holding T_{k-2}
        cheb_step_kernel<<<grid, NTHREADS, SMEM_BYTES>>>(out, k, k & 1, (k + 1) & 1, k & 1);
    }
}

// round 13
// speedup vs baseline: 2.9506x; 1.1524x over previous
#include <cuda_runtime.h>
#include <cuda_bf16.h>
#include <stdint.h>

#define N      4096
#define NN     ((size_t)N * N)
#define NF     4
#define NC     33
#define KC     64                  // K elements per pipeline stage
#define NCHUNK (N / KC)            // 64
#define NSTAGE 3
#define TILE_B (128 * 128)         // 128 rows x 128 bytes = 16 KB per matrix tile
#define STAGE_B (4 * TILE_B)       // Ah, Al, Bh, Bl = 64 KB
#define SMEM_BYTES (NSTAGE * STAGE_B)   // 192 KB
#define NTHREADS 512

// ---------------- device globals (scratch; no allocation allowed) ----------
// All 33 Chebyshev matrices kept as bf16 hi/lo splits (k-indexed, no ping-pong)
__device__ __align__(1024) __nv_bfloat16  g_Th[NC][NN];   // T_k hi
__device__ __align__(1024) __nv_bfloat16  g_Tl[NC][NN];   // T_k lo
__device__ __align__(1024) __nv_bfloat16  g_Fh[NN];       // F = 2(L-I) hi
__device__ __align__(1024) __nv_bfloat16  g_Fl[NN];       // F lo
__device__ float g_coef[NC][NF];

// ---------------- PTX helpers (baseline sm_80+ PTX only) -------------------
__device__ __forceinline__ uint32_t smem_u32(const void* p) {
    uint32_t a;
    asm("{ .reg .u64 t; cvta.to.shared.u64 t, %1; cvt.u32.u64 %0, t; }" : "=r"(a) : "l"(p));
    return a;
}

#define CP_ASYNC16(dst, src) \
    asm volatile("cp.async.cg.shared.global [%0], [%1], 16;" :: "r"(dst), "l"(src) : "memory")
#define CP_COMMIT() asm volatile("cp.async.commit_group;" ::: "memory")
#define CP_WAIT(n)  asm volatile("cp.async.wait_group %0;" :: "n"(n) : "memory")

#define LDSM_X4(r, addr)                                                     \
    asm volatile("ldmatrix.sync.aligned.m8n8.x4.shared.b16 {%0,%1,%2,%3}, [%4];" \
        : "=r"((r)[0]), "=r"((r)[1]), "=r"((r)[2]), "=r"((r)[3]) : "r"(addr))

#define MMA_BF16(c, a, b)                                                    \
    asm volatile("mma.sync.aligned.m16n8k16.row.col.f32.bf16.bf16.f32 "      \
        "{%0,%1,%2,%3}, {%4,%5,%6,%7}, {%8,%9}, {%0,%1,%2,%3};"              \
        : "+f"((c)[0]), "+f"((c)[1]), "+f"((c)[2]), "+f"((c)[3])             \
        : "r"((a)[0]), "r"((a)[1]), "r"((a)[2]), "r"((a)[3]),                \
          "r"((b)[0]), "r"((b)[1]))

// ---------------- coefficients --------------------------------------------
__global__ void coeff_kernel() {
    const int o = threadIdx.x;
    if (o >= NC) return;
    const double PI = 3.14159265358979323846;
    const double taus[NF] = {0.5, 1.0, 2.0, 4.0};
    double sums[NF] = {0, 0, 0, 0};
    for (int j = 0; j < NC; j++) {
        double node = cos(PI * (j + 0.5) / NC);
        double x    = node + 1.0;
        double t    = cos(PI * (double)o * (j + 0.5) / NC);
        #pragma unroll
        for (int f = 0; f < NF; f++) sums[f] += t * exp(-taus[f] * x);
    }
    double scale = (2.0 / NC) * 64.0;     // * sqrt(4096)
    if (o == 0) scale *= 0.5;             // r0 uses 0.5*c[0]
    #pragma unroll
    for (int f = 0; f < NF; f++) g_coef[o][f] = (float)(scale * sums[f]);
}

// ---------------- init: splits of T0=I, T1=L-I, F=2(L-I) -------------------
__global__ void init_kernel(const float* __restrict__ L) {
    size_t v = ((size_t)blockIdx.x * blockDim.x + threadIdx.x) * 4;
    if (v >= NN) return;
    const int i  = (int)(v / N);
    const int j0 = (int)(v % N);
    float4 l = *(const float4*)(L + v);
    float d[4], t1[4];
    #pragma unroll
    for (int t = 0; t < 4; t++) d[t] = (j0 + t == i) ? 1.0f : 0.0f;
    t1[0] = l.x - d[0]; t1[1] = l.y - d[1]; t1[2] = l.z - d[2]; t1[3] = l.w - d[3];

    #pragma unroll
    for (int t = 0; t < 4; t++) {
        // T0 = I (exact in bf16, lo = 0)
        g_Th[0][v + t] = __float2bfloat16(d[t]);
        g_Tl[0][v + t] = __float2bfloat16(0.0f);
        // T1 = L - I split
        __nv_bfloat16 h  = __float2bfloat16(t1[t]);
        __nv_bfloat16 lo = __float2bfloat16(t1[t] - __bfloat162float(h));
        g_Th[1][v + t] = h; g_Tl[1][v + t] = lo;
        // F = 2(L-I) split
        float f = 2.0f * t1[t];
        __nv_bfloat16 fh = __float2bfloat16(f);
        __nv_bfloat16 fl = __float2bfloat16(f - __bfloat162float(fh));
        g_Fh[v + t] = fh; g_Fl[v + t] = fl;
    }
}

// ---------------- main step: D = F @ T_{k-1}; T_k = D - T_{k-2} ------------
// D[m][n] = sum_k F[m][k] * T[n][k]  (T symmetric => equals F @ T)
// 16 warps in a 4x4 grid; each warp owns a 32x32 output tile (2 mt x 4 nt).
__global__ __launch_bounds__(NTHREADS, 1)
void cheb_step_kernel(int k)
{
    extern __shared__ __align__(128) char smem[];
    const uint32_t sbase = smem_u32(smem);
    const int tid  = threadIdx.x;
    const int wid  = tid >> 5;
    const int lane = tid & 31;
    const int wm   = wid >> 2;        // 0..3  (M direction, 32 rows each)
    const int wn   = wid & 3;         // 0..3  (N direction, 32 cols each)
    const int bn0  = blockIdx.x * 128;
    const int bm0  = blockIdx.y * 128;

    const __nv_bfloat16* srcs[4];
    srcs[0] = g_Fh          + (size_t)bm0 * N;
    srcs[1] = g_Fl          + (size_t)bm0 * N;
    srcs[2] = g_Th[k - 1]   + (size_t)bn0 * N;
    srcs[3] = g_Tl[k - 1]   + (size_t)bn0 * N;

    // stage fill: 4 tiles x 128 rows x 8 segs of 16B, xor-swizzled per row.
    auto load_stage = [&](int s, int chunk) {
        const uint32_t sb   = sbase + s * STAGE_B;
        const size_t   koff = (size_t)chunk * KC;
        #pragma unroll
        for (int t = 0; t < 4; t++) {
            const uint32_t tb = sb + t * TILE_B;
            const __nv_bfloat16* src = srcs[t] + koff;
            #pragma unroll
            for (int q = 0; q < 2; q++) {
                const int s16 = tid + q * NTHREADS;     // 0..1023
                const int row = s16 >> 3, seg = s16 & 7;
                CP_ASYNC16(tb + row * 128 + ((seg ^ (row & 7)) << 4),
                           src + (size_t)row * N + seg * 8);
            }
        }
    };

    float acc[2][4][4];
    #pragma unroll
    for (int mt = 0; mt < 2; mt++)
        #pragma unroll
        for (int nt = 0; nt < 4; nt++)
            #pragma unroll
            for (int q = 0; q < 4; q++) acc[mt][nt][q] = 0.0f;

    load_stage(0, 0); CP_COMMIT();
    load_stage(1, 1); CP_COMMIT();

    const int arow_l = lane & 15;                 // A ldmatrix row-in-tile
    const int asub   = lane >> 4;                 // A k-half
    const int browx  = ((lane >> 4) << 3) + (lane & 7);   // B X4 row offset 0..15
    const int bkh    = (lane >> 3) & 1;           // B k-half

    for (int i = 0; i < NCHUNK; i++) {
        CP_WAIT(1);
        __syncthreads();                    // stage i landed; i-1 compute done
        if (i + 2 < NCHUNK) load_stage((i + 2) % NSTAGE, i + 2);
        CP_COMMIT();

        const uint32_t stb = sbase + (i % NSTAGE) * STAGE_B;
        const uint32_t Ah = stb;
        const uint32_t Al = stb + TILE_B;
        const uint32_t Bh = stb + 2 * TILE_B;
        const uint32_t Bl = stb + 3 * TILE_B;

        #pragma unroll
        for (int ks = 0; ks < 4; ks++) {    // 4 x k16 within the 64-chunk
            uint32_t ah[2][4], al[2][4], b[4][2];
            // ---- pass 1: Ah * Bh ----
            #pragma unroll
            for (int mt = 0; mt < 2; mt++) {
                const int row = wm * 32 + mt * 16 + arow_l;
                const int seg = ks * 2 + asub;
                LDSM_X4(ah[mt], Ah + row * 128 + ((seg ^ (row & 7)) << 4));
            }
            #pragma unroll
            for (int np = 0; np < 2; np++) {   // two nt tiles per X4
                const int row = wn * 32 + np * 16 + browx;
                const int seg = ks * 2 + bkh;
                LDSM_X4(&b[np * 2][0], Bh + row * 128 + ((seg ^ (row & 7)) << 4));
            }
            #pragma unroll
            for (int mt = 0; mt < 2; mt++)
                #pragma unroll
                for (int nt = 0; nt < 4; nt++)
                    MMA_BF16(acc[mt][nt], ah[mt], b[nt]);   // Ah*Bh

            // ---- pass 2: Al * Bh (reuse b) ----
            #pragma unroll
            for (int mt = 0; mt < 2; mt++) {
                const int row = wm * 32 + mt * 16 + arow_l;
                const int seg = ks * 2 + asub;
                LDSM_X4(al[mt], Al + row * 128 + ((seg ^ (row & 7)) << 4));
            }
            #pragma unroll
            for (int mt = 0; mt < 2; mt++)
                #pragma unroll
                for (int nt = 0; nt < 4; nt++)
                    MMA_BF16(acc[mt][nt], al[mt], b[nt]);   // Al*Bh

            // ---- pass 3: Ah * Bl (reuse ah, reload b) ----
            #pragma unroll
            for (int np = 0; np < 2; np++) {
                const int row = wn * 32 + np * 16 + browx;
                const int seg = ks * 2 + bkh;
                LDSM_X4(&b[np * 2][0], Bl + row * 128 + ((seg ^ (row & 7)) << 4));
            }
            #pragma unroll
            for (int mt = 0; mt < 2; mt++)
                #pragma unroll
                for (int nt = 0; nt < 4; nt++)
                    MMA_BF16(acc[mt][nt], ah[mt], b[nt]);   // Ah*Bl
        }
    }

    // ---------------- lean epilogue: T_k = D - T_{k-2}, store hi/lo --------
    const __nv_bfloat16* __restrict__ ThOld = g_Th[k - 2];
    const __nv_bfloat16* __restrict__ TlOld = g_Tl[k - 2];
    __nv_bfloat16* __restrict__ ThNew = g_Th[k];
    __nv_bfloat16* __restrict__ TlNew = g_Tl[k];

    #pragma unroll
    for (int mt = 0; mt < 2; mt++) {
        const int r0 = bm0 + wm * 32 + mt * 16 + (lane >> 2);
        #pragma unroll
        for (int nt = 0; nt < 4; nt++) {
            const int col = bn0 + wn * 32 + nt * 8 + (lane & 3) * 2;
            #pragma unroll
            for (int p = 0; p < 2; p++) {             // rows r0 and r0+8
                const size_t idx = (size_t)(r0 + p * 8) * N + col;
                __nv_bfloat162 oh = *(const __nv_bfloat162*)(ThOld + idx);
                __nv_bfloat162 ol = *(const __nv_bfloat162*)(TlOld + idx);
                const float tnx = acc[mt][nt][p * 2 + 0]
                                  - (__bfloat162float(oh.x) + __bfloat162float(ol.x));
                const float tny = acc[mt][nt][p * 2 + 1]
                                  - (__bfloat162float(oh.y) + __bfloat162float(ol.y));

                __nv_bfloat16 hx = __float2bfloat16(tnx);
                __nv_bfloat16 hy = __float2bfloat16(tny);
                __nv_bfloat16 lx = __float2bfloat16(tnx - __bfloat162float(hx));
                __nv_bfloat16 ly = __float2bfloat16(tny - __bfloat162float(hy));
                *(__nv_bfloat162*)(ThNew + idx) = __nv_bfloat162(hx, hy);
                *(__nv_bfloat162*)(TlNew + idx) = __nv_bfloat162(lx, ly);
            }
        }
    }
}

// ---------------- final: out[f] = sum_k c[k][f] * (Th[k]+Tl[k]) ------------
__global__ void final_kernel(float* __restrict__ out) {
    size_t v = ((size_t)blockIdx.x * blockDim.x + threadIdx.x) * 4;
    if (v >= NN) return;
    float s[NF][4];
    #pragma unroll
    for (int f = 0; f < NF; f++)
        #pragma unroll
        for (int j = 0; j < 4; j++) s[f][j] = 0.0f;

    for (int k = 0; k < NC; k++) {
        uint2 hraw = *(const uint2*)(&g_Th[k][v]);
        uint2 lraw = *(const uint2*)(&g_Tl[k][v]);
        __nv_bfloat162 h0 = *(__nv_bfloat162*)&hraw.x;
        __nv_bfloat162 h1 = *(__nv_bfloat162*)&hraw.y;
        __nv_bfloat162 l0 = *(__nv_bfloat162*)&lraw.x;
        __nv_bfloat162 l1 = *(__nv_bfloat162*)&lraw.y;
        float t[4];
        t[0] = __bfloat162float(h0.x) + __bfloat162float(l0.x);
        t[1] = __bfloat162float(h0.y) + __bfloat162float(l0.y);
        t[2] = __bfloat162float(h1.x) + __bfloat162float(l1.x);
        t[3] = __bfloat162float(h1.y) + __bfloat162float(l1.y);
        #pragma unroll
        for (int f = 0; f < NF; f++) {
            const float c = g_coef[k][f];
            #pragma unroll
            for (int j = 0; j < 4; j++) s[f][j] += c * t[j];
        }
    }
    #pragma unroll
    for (int f = 0; f < NF; f++)
        *(float4*)(out + (size_t)f * NN + v) = make_float4(s[f][0], s[f][1], s[f][2], s[f][3]);
}

// ---------------------------------------------------------------------------
extern "C" void kernel_launch(void* const* d_in, const int* in_sizes, int n_in,
                              void* d_out, int out_size)
{
    const float* L = (const float*)d_in[0];
    float* out = (float*)d_out;

    cudaFuncSetAttribute(cheb_step_kernel,
                         cudaFuncAttributeMaxDynamicSharedMemorySize, SMEM_BYTES);

    coeff_kernel<<<1, 64>>>();
    init_kernel<<<(int)((NN / 4 + 255) / 256), 256>>>(L);

    dim3 grid(N / 128, N / 128);
    for (int k = 2; k <= 32; k++)
        cheb_step_kernel<<<grid, NTHREADS, SMEM_BYTES>>>(k);

    final_kernel<<<(int)((NN / 4 + 255) / 256), 256>>>(out);
}

// round 14
// speedup vs baseline: 5.0769x; 1.7206x over previous
#include <cuda_runtime.h>
#include <cuda_bf16.h>
#include <stdint.h>

#define N      4096
#define NN     ((size_t)N * N)
#define NF     4
#define NC     33
#define KC     64                  // K elements per pipeline stage
#define NCHUNK (N / KC)            // 64
#define NSTAGE 3
#define TILE_B (128 * 128)         // 128 rows x 128 bytes = 16 KB per matrix tile
#define STAGE_B (4 * TILE_B)       // Ah, Al, Bh, Bl = 64 KB
#define SMEM_BYTES (NSTAGE * STAGE_B)   // 192 KB (also reused for mirror transpose)
#define NTHREADS 512
#define NBLK   (N / 128)           // 32 block-rows
#define NTRI   (NBLK * (NBLK + 1) / 2)   // 528 lower-triangle tiles

// ---------------- device globals (scratch; no allocation allowed) ----------
__device__ __align__(1024) __nv_bfloat16  g_Th[NC][NN];   // T_k hi
__device__ __align__(1024) __nv_bfloat16  g_Tl[NC][NN];   // T_k lo
__device__ __align__(1024) __nv_bfloat16  g_Fh[NN];       // F = 2(L-I) hi
__device__ __align__(1024) __nv_bfloat16  g_Fl[NN];       // F lo
__device__ float g_coef[NC][NF];

// ---------------- PTX helpers (baseline sm_80+ PTX only) -------------------
__device__ __forceinline__ uint32_t smem_u32(const void* p) {
    uint32_t a;
    asm("{ .reg .u64 t; cvta.to.shared.u64 t, %1; cvt.u32.u64 %0, t; }" : "=r"(a) : "l"(p));
    return a;
}

#define CP_ASYNC16(dst, src) \
    asm volatile("cp.async.cg.shared.global [%0], [%1], 16;" :: "r"(dst), "l"(src) : "memory")
#define CP_COMMIT() asm volatile("cp.async.commit_group;" ::: "memory")
#define CP_WAIT(n)  asm volatile("cp.async.wait_group %0;" :: "n"(n) : "memory")

#define LDSM_X4(r, addr)                                                     \
    asm volatile("ldmatrix.sync.aligned.m8n8.x4.shared.b16 {%0,%1,%2,%3}, [%4];" \
        : "=r"((r)[0]), "=r"((r)[1]), "=r"((r)[2]), "=r"((r)[3]) : "r"(addr))

#define MMA_BF16(c, a, b)                                                    \
    asm volatile("mma.sync.aligned.m16n8k16.row.col.f32.bf16.bf16.f32 "      \
        "{%0,%1,%2,%3}, {%4,%5,%6,%7}, {%8,%9}, {%0,%1,%2,%3};"              \
        : "+f"((c)[0]), "+f"((c)[1]), "+f"((c)[2]), "+f"((c)[3])             \
        : "r"((a)[0]), "r"((a)[1]), "r"((a)[2]), "r"((a)[3]),                \
          "r"((b)[0]), "r"((b)[1]))

// ---------------- coefficients --------------------------------------------
__global__ void coeff_kernel() {
    const int o = threadIdx.x;
    if (o >= NC) return;
    const double PI = 3.14159265358979323846;
    const double taus[NF] = {0.5, 1.0, 2.0, 4.0};
    double sums[NF] = {0, 0, 0, 0};
    for (int j = 0; j < NC; j++) {
        double node = cos(PI * (j + 0.5) / NC);
        double x    = node + 1.0;
        double t    = cos(PI * (double)o * (j + 0.5) / NC);
        #pragma unroll
        for (int f = 0; f < NF; f++) sums[f] += t * exp(-taus[f] * x);
    }
    double scale = (2.0 / NC) * 64.0;     // * sqrt(4096)
    if (o == 0) scale *= 0.5;             // r0 uses 0.5*c[0]
    #pragma unroll
    for (int f = 0; f < NF; f++) g_coef[o][f] = (float)(scale * sums[f]);
}

// ---------------- init: splits of T0=I, T1=L-I, F=2(L-I) -------------------
__global__ void init_kernel(const float* __restrict__ L) {
    size_t v = ((size_t)blockIdx.x * blockDim.x + threadIdx.x) * 4;
    if (v >= NN) return;
    const int i  = (int)(v / N);
    const int j0 = (int)(v % N);
    float4 l = *(const float4*)(L + v);
    float d[4], t1[4];
    #pragma unroll
    for (int t = 0; t < 4; t++) d[t] = (j0 + t == i) ? 1.0f : 0.0f;
    t1[0] = l.x - d[0]; t1[1] = l.y - d[1]; t1[2] = l.z - d[2]; t1[3] = l.w - d[3];

    #pragma unroll
    for (int t = 0; t < 4; t++) {
        g_Th[0][v + t] = __float2bfloat16(d[t]);
        g_Tl[0][v + t] = __float2bfloat16(0.0f);
        __nv_bfloat16 h  = __float2bfloat16(t1[t]);
        __nv_bfloat16 lo = __float2bfloat16(t1[t] - __bfloat162float(h));
        g_Th[1][v + t] = h; g_Tl[1][v + t] = lo;
        float f = 2.0f * t1[t];
        __nv_bfloat16 fh = __float2bfloat16(f);
        __nv_bfloat16 fl = __float2bfloat16(f - __bfloat162float(fh));
        g_Fh[v + t] = fh; g_Fl[v + t] = fl;
    }
}

// ---------------- main step: lower-triangle blocks of D = F @ T_{k-1} ------
// T_k = D - T_{k-2}; block (i,j) computed, block (j,i) mirrored via smem.
__global__ __launch_bounds__(NTHREADS, 1)
void cheb_step_kernel(int k)
{
    extern __shared__ __align__(128) char smem[];
    const uint32_t sbase = smem_u32(smem);
    const int tid  = threadIdx.x;
    const int wid  = tid >> 5;
    const int lane = tid & 31;
    const int wm   = wid >> 2;        // 0..3  (M direction, 32 rows each)
    const int wn   = wid & 3;         // 0..3  (N direction, 32 cols each)

    // triangular decode: block (bi, bj), bi >= bj
    int bi = (int)((sqrtf(8.0f * blockIdx.x + 1.0f) - 1.0f) * 0.5f);
    while ((bi + 1) * (bi + 2) / 2 <= (int)blockIdx.x) bi++;
    while (bi * (bi + 1) / 2 > (int)blockIdx.x) bi--;
    const int bj  = blockIdx.x - bi * (bi + 1) / 2;
    const int bm0 = bi * 128;         // F row block (output rows)
    const int bn0 = bj * 128;         // T row block (output cols)
    const bool diag = (bi == bj);

    const __nv_bfloat16* srcs[4];
    srcs[0] = g_Fh        + (size_t)bm0 * N;
    srcs[1] = g_Fl        + (size_t)bm0 * N;
    srcs[2] = g_Th[k - 1] + (size_t)bn0 * N;
    srcs[3] = g_Tl[k - 1] + (size_t)bn0 * N;

    auto load_stage = [&](int s, int chunk) {
        const uint32_t sb   = sbase + s * STAGE_B;
        const size_t   koff = (size_t)chunk * KC;
        #pragma unroll
        for (int t = 0; t < 4; t++) {
            const uint32_t tb = sb + t * TILE_B;
            const __nv_bfloat16* src = srcs[t] + koff;
            #pragma unroll
            for (int q = 0; q < 2; q++) {
                const int s16 = tid + q * NTHREADS;     // 0..1023
                const int row = s16 >> 3, seg = s16 & 7;
                CP_ASYNC16(tb + row * 128 + ((seg ^ (row & 7)) << 4),
                           src + (size_t)row * N + seg * 8);
            }
        }
    };

    float acc[2][4][4];
    #pragma unroll
    for (int mt = 0; mt < 2; mt++)
        #pragma unroll
        for (int nt = 0; nt < 4; nt++)
            #pragma unroll
            for (int q = 0; q < 4; q++) acc[mt][nt][q] = 0.0f;

    load_stage(0, 0); CP_COMMIT();
    load_stage(1, 1); CP_COMMIT();

    const int arow_l = lane & 15;
    const int asub   = lane >> 4;
    const int browx  = ((lane >> 4) << 3) + (lane & 7);   // B X4 row offset 0..15
    const int bkh    = (lane >> 3) & 1;

    for (int i = 0; i < NCHUNK; i++) {
        CP_WAIT(1);
        __syncthreads();
        if (i + 2 < NCHUNK) load_stage((i + 2) % NSTAGE, i + 2);
        CP_COMMIT();

        const uint32_t stb = sbase + (i % NSTAGE) * STAGE_B;
        const uint32_t Ah = stb;
        const uint32_t Al = stb + TILE_B;
        const uint32_t Bh = stb + 2 * TILE_B;
        const uint32_t Bl = stb + 3 * TILE_B;

        #pragma unroll
        for (int ks = 0; ks < 4; ks++) {
            uint32_t ah[2][4], al[2][4], b[4][2];
            #pragma unroll
            for (int mt = 0; mt < 2; mt++) {
                const int row = wm * 32 + mt * 16 + arow_l;
                const int seg = ks * 2 + asub;
                LDSM_X4(ah[mt], Ah + row * 128 + ((seg ^ (row & 7)) << 4));
            }
            #pragma unroll
            for (int np = 0; np < 2; np++) {
                const int row = wn * 32 + np * 16 + browx;
                const int seg = ks * 2 + bkh;
                LDSM_X4(&b[np * 2][0], Bh + row * 128 + ((seg ^ (row & 7)) << 4));
            }
            #pragma unroll
            for (int mt = 0; mt < 2; mt++)
                #pragma unroll
                for (int nt = 0; nt < 4; nt++)
                    MMA_BF16(acc[mt][nt], ah[mt], b[nt]);   // Ah*Bh

            #pragma unroll
            for (int mt = 0; mt < 2; mt++) {
                const int row = wm * 32 + mt * 16 + arow_l;
                const int seg = ks * 2 + asub;
                LDSM_X4(al[mt], Al + row * 128 + ((seg ^ (row & 7)) << 4));
            }
            #pragma unroll
            for (int mt = 0; mt < 2; mt++)
                #pragma unroll
                for (int nt = 0; nt < 4; nt++)
                    MMA_BF16(acc[mt][nt], al[mt], b[nt]);   // Al*Bh

            #pragma unroll
            for (int np = 0; np < 2; np++) {
                const int row = wn * 32 + np * 16 + browx;
                const int seg = ks * 2 + bkh;
                LDSM_X4(&b[np * 2][0], Bl + row * 128 + ((seg ^ (row & 7)) << 4));
            }
            #pragma unroll
            for (int mt = 0; mt < 2; mt++)
                #pragma unroll
                for (int nt = 0; nt < 4; nt++)
                    MMA_BF16(acc[mt][nt], ah[mt], b[nt]);   // Ah*Bl
        }
    }

    // All warps done with pipeline smem before the mirror tile overwrites it.
    __syncthreads();

    // smem reuse for mirror: ThT tile (32KB) then TlT tile (32KB)
    const uint32_t ThT = sbase;
    const uint32_t TlT = sbase + 32768;

    const __nv_bfloat16* __restrict__ ThOld = g_Th[k - 2];
    const __nv_bfloat16* __restrict__ TlOld = g_Tl[k - 2];
    __nv_bfloat16* __restrict__ ThNew = g_Th[k];
    __nv_bfloat16* __restrict__ TlNew = g_Tl[k];

    #pragma unroll
    for (int mt = 0; mt < 2; mt++) {
        const int lr0 = wm * 32 + mt * 16 + (lane >> 2);   // local row in tile
        #pragma unroll
        for (int nt = 0; nt < 4; nt++) {
            const int lc = wn * 32 + nt * 8 + (lane & 3) * 2;  // local col
            #pragma unroll
            for (int p = 0; p < 2; p++) {
                const int lr = lr0 + p * 8;
                const size_t idx = (size_t)(bm0 + lr) * N + bn0 + lc;
                __nv_bfloat162 oh = *(const __nv_bfloat162*)(ThOld + idx);
                __nv_bfloat162 ol = *(const __nv_bfloat162*)(TlOld + idx);
                const float tnx = acc[mt][nt][p * 2 + 0]
                                  - (__bfloat162float(oh.x) + __bfloat162float(ol.x));
                const float tny = acc[mt][nt][p * 2 + 1]
                                  - (__bfloat162float(oh.y) + __bfloat162float(ol.y));

                __nv_bfloat16 hx = __float2bfloat16(tnx);
                __nv_bfloat16 hy = __float2bfloat16(tny);
                __nv_bfloat16 lx = __float2bfloat16(tnx - __bfloat162float(hx));
                __nv_bfloat16 ly = __float2bfloat16(tny - __bfloat162float(hy));
                *(__nv_bfloat162*)(ThNew + idx) = __nv_bfloat162(hx, hy);
                *(__nv_bfloat162*)(TlNew + idx) = __nv_bfloat162(lx, ly);

                if (!diag) {
                    // transposed staging: [col][row], 2B scalar stores
                    asm volatile("st.shared.b16 [%0], %1;" ::
                        "r"(ThT + (lc * 128 + lr) * 2), "h"(*(uint16_t*)&hx));
                    asm volatile("st.shared.b16 [%0], %1;" ::
                        "r"(ThT + ((lc + 1) * 128 + lr) * 2), "h"(*(uint16_t*)&hy));
                    asm volatile("st.shared.b16 [%0], %1;" ::
                        "r"(TlT + (lc * 128 + lr) * 2), "h"(*(uint16_t*)&lx));
                    asm volatile("st.shared.b16 [%0], %1;" ::
                        "r"(TlT + ((lc + 1) * 128 + lr) * 2), "h"(*(uint16_t*)&ly));
                }
            }
        }
    }

    if (!diag) {
        __syncthreads();
        // coalesced mirror write: block (bj, bi); 4096 16B-chunks over 512 thr
        #pragma unroll
        for (int q = 0; q < 8; q++) {
            const int c   = tid + q * NTHREADS;       // 0..4095
            const int arr = c >> 11;                  // 0: hi, 1: lo
            const int rem = c & 2047;
            const int row = rem >> 4;                 // 0..127
            const int seg = rem & 15;                 // 16B segment
            uint32_t srcs_ = (arr ? TlT : ThT) + row * 256 + seg * 16;
            uint4 val;
            asm volatile("ld.shared.v4.u32 {%0,%1,%2,%3}, [%4];"
                : "=r"(val.x), "=r"(val.y), "=r"(val.z), "=r"(val.w) : "r"(srcs_));
            __nv_bfloat16* dst = (arr ? TlNew : ThNew);
            *(uint4*)(dst + (size_t)(bn0 + row) * N + bm0 + seg * 8) = val;
        }
    }
}

// ---------------- final: out[f] = sum_k c[k][f] * (Th[k]+Tl[k]) ------------
__global__ void final_kernel(float* __restrict__ out) {
    size_t v = ((size_t)blockIdx.x * blockDim.x + threadIdx.x) * 4;
    if (v >= NN) return;
    float s[NF][4];
    #pragma unroll
    for (int f = 0; f < NF; f++)
        #pragma unroll
        for (int j = 0; j < 4; j++) s[f][j] = 0.0f;

    for (int k = 0; k < NC; k++) {
        uint2 hraw = *(const uint2*)(&g_Th[k][v]);
        uint2 lraw = *(const uint2*)(&g_Tl[k][v]);
        __nv_bfloat162 h0 = *(__nv_bfloat162*)&hraw.x;
        __nv_bfloat162 h1 = *(__nv_bfloat162*)&hraw.y;
        __nv_bfloat162 l0 = *(__nv_bfloat162*)&lraw.x;
        __nv_bfloat162 l1 = *(__nv_bfloat162*)&lraw.y;
        float t[4];
        t[0] = __bfloat162float(h0.x) + __bfloat162float(l0.x);
        t[1] = __bfloat162float(h0.y) + __bfloat162float(l0.y);
        t[2] = __bfloat162float(h1.x) + __bfloat162float(l1.x);
        t[3] = __bfloat162float(h1.y) + __bfloat162float(l1.y);
        #pragma unroll
        for (int f = 0; f < NF; f++) {
            const float c = g_coef[k][f];
            #pragma unroll
            for (int j = 0; j < 4; j++) s[f][j] += c * t[j];
        }
    }
    #pragma unroll
    for (int f = 0; f < NF; f++)
        *(float4*)(out + (size_t)f * NN + v) = make_float4(s[f][0], s[f][1], s[f][2], s[f][3]);
}

// ---------------------------------------------------------------------------
extern "C" void kernel_launch(void* const* d_in, const int* in_sizes, int n_in,
                              void* d_out, int out_size)
{
    const float* L = (const float*)d_in[0];
    float* out = (float*)d_out;

    cudaFuncSetAttribute(cheb_step_kernel,
                         cudaFuncAttributeMaxDynamicSharedMemorySize, SMEM_BYTES);

    coeff_kernel<<<1, 64>>>();
    init_kernel<<<(int)((NN / 4 + 255) / 256), 256>>>(L);

    for (int k = 2; k <= 32; k++)
        cheb_step_kernel<<<NTRI, NTHREADS, SMEM_BYTES>>>(k);

    final_kernel<<<(int)((NN / 4 + 255) / 256), 256>>>(out);
}